// round 10
// baseline (speedup 1.0000x reference)
#include <cuda_runtime.h>
#include <cuda_bf16.h>
#include <math.h>
#include <stdint.h>

// ---------------- problem constants ----------------
constexpr int   BN      = 8192;
constexpr int   DD      = 256;
constexpr int   NS      = 64;
constexpr float INV_TAU = 1.0f / 0.07f;
constexpr float MARGIN  = 0.2f;
constexpr int   BK      = 64;          // bf16 per K-chunk (128 bytes)
constexpr int   NIT     = DD / BK;     // 4
constexpr int   STAGES  = 3;
// CTA tile: 128 x 128, 4 warps (2m x 2n), warp tile 64x64

// ---------------- device scratch ----------------
__device__ __align__(16) __nv_bfloat16 g_Abf[(size_t)BN * DD];
__device__ __align__(16) __nv_bfloat16 g_Bbf[(size_t)BN * DD];

__device__ float g_rowexp[BN];
__device__ float g_colexp[BN];
__device__ float g_rowsum[BN];
__device__ float g_rowsame[BN];
__device__ float g_diag[BN];
__device__ float g_cnt[NS];
__device__ float g_segv[NS];
__device__ float g_segt[NS];
__device__ float g_tri[2];

// ---------------- small zero: NS-sized arrays + tri ----------------
__global__ void zero_small_kernel() {
    int i = threadIdx.x;
    if (i < NS) { g_cnt[i] = 0.f; g_segv[i] = 0.f; g_segt[i] = 0.f; }
    if (i < 2)  g_tri[i] = 0.f;
}

// ---------------- prep: convert fp32->bf16, exact diag, counts, zero row stats ----
// one warp per row; 8 warps per CTA
__global__ void prep_kernel(const float* __restrict__ S,
                            const float* __restrict__ T,
                            const int* __restrict__ ids) {
    const int warp = threadIdx.x >> 5;
    const int lane = threadIdx.x & 31;
    const int row  = blockIdx.x * 8 + warp;

    const float4* s4 = (const float4*)(S + (size_t)row * DD);
    const float4* t4 = (const float4*)(T + (size_t)row * DD);
    float4 s0 = s4[lane * 2], s1 = s4[lane * 2 + 1];
    float4 t0 = t4[lane * 2], t1 = t4[lane * 2 + 1];

    __align__(16) __nv_bfloat162 sb[4];
    __align__(16) __nv_bfloat162 tb[4];
    sb[0] = __floats2bfloat162_rn(s0.x, s0.y);
    sb[1] = __floats2bfloat162_rn(s0.z, s0.w);
    sb[2] = __floats2bfloat162_rn(s1.x, s1.y);
    sb[3] = __floats2bfloat162_rn(s1.z, s1.w);
    tb[0] = __floats2bfloat162_rn(t0.x, t0.y);
    tb[1] = __floats2bfloat162_rn(t0.z, t0.w);
    tb[2] = __floats2bfloat162_rn(t1.x, t1.y);
    tb[3] = __floats2bfloat162_rn(t1.z, t1.w);
    *(uint4*)&g_Abf[(size_t)row * DD + lane * 8] = *(const uint4*)sb;
    *(uint4*)&g_Bbf[(size_t)row * DD + lane * 8] = *(const uint4*)tb;

    float dot = s0.x * t0.x + s0.y * t0.y + s0.z * t0.z + s0.w * t0.w
              + s1.x * t1.x + s1.y * t1.y + s1.z * t1.z + s1.w * t1.w;
    #pragma unroll
    for (int o = 16; o > 0; o >>= 1)
        dot += __shfl_xor_sync(0xffffffffu, dot, o);

    if (lane == 0) {
        g_diag[row] = dot;
        atomicAdd(&g_cnt[ids[row]], 1.0f);
        g_rowexp[row]  = 0.f;
        g_colexp[row]  = 0.f;
        g_rowsum[row]  = 0.f;
        g_rowsame[row] = 0.f;
    }
}

// ---------------- PTX helpers ----------------
__device__ __forceinline__ uint32_t smem_u32(const void* p) {
    uint32_t a;
    asm("{ .reg .u64 t; cvta.to.shared.u64 t, %1; cvt.u32.u64 %0, t; }"
        : "=r"(a) : "l"(p));
    return a;
}
__device__ __forceinline__ void cp16(uint32_t dst, const void* src) {
    asm volatile("cp.async.cg.shared.global [%0], [%1], 16;" :: "r"(dst), "l"(src));
}
template<int N> __device__ __forceinline__ void cp_wait() {
    asm volatile("cp.async.wait_group %0;" :: "n"(N) : "memory");
}
__device__ __forceinline__ void ldsm_x4(uint32_t* r, uint32_t addr) {
    asm volatile("ldmatrix.sync.aligned.m8n8.x4.shared.b16 {%0,%1,%2,%3}, [%4];"
                 : "=r"(r[0]), "=r"(r[1]), "=r"(r[2]), "=r"(r[3]) : "r"(addr));
}
__device__ __forceinline__ void mma16816(float* d, const uint32_t* a, const uint32_t* b) {
    asm volatile(
        "mma.sync.aligned.m16n8k16.row.col.f32.bf16.bf16.f32 "
        "{%0,%1,%2,%3}, {%4,%5,%6,%7}, {%8,%9}, {%0,%1,%2,%3};"
        : "+f"(d[0]), "+f"(d[1]), "+f"(d[2]), "+f"(d[3])
        : "r"(a[0]), "r"(a[1]), "r"(a[2]), "r"(a[3]), "r"(b[0]), "r"(b[1]));
}

// SW128 swizzle: [rows x 128B] tile; r = row, q = 16B chunk (0..7)
__device__ __forceinline__ uint32_t swz(int r, int q) {
    return (uint32_t)(r * 128 + ((q ^ (r & 7)) << 4));
}

// dynamic smem layout (bytes): 3 stages of (A 16KB + B 16KB), then stats
constexpr int STG     = 32768;
constexpr int ST_OFF  = STAGES * STG;                  // 98304
constexpr int SMEM_DYN = ST_OFF + 5 * 512;             // 100864

// ---------------- main bf16 mma.sync GEMM + fused epilogue ----------------
// 128 threads, 4 warps (2m x 2n), warp tile 64x64
__global__ void __launch_bounds__(128, 2)
gemm_kernel(const int* __restrict__ ids) {
    extern __shared__ char smem[];
    const uint32_t sbase = smem_u32(smem);
    float* s_rexp  = (float*)(smem + ST_OFF);
    float* s_rsum  = (float*)(smem + ST_OFF + 512);
    float* s_rsame = (float*)(smem + ST_OFF + 1024);
    float* s_cexp  = (float*)(smem + ST_OFF + 1536);
    int*   s_idc   = (int*)  (smem + ST_OFF + 2048);

    const int tid  = threadIdx.x;
    const int wid  = tid >> 5;
    const int lane = tid & 31;
    const int wm   = wid & 1;        // warp m index (2)
    const int wn   = wid >> 1;       // warp n index (2)
    const int row0 = blockIdx.y * 128;
    const int col0 = blockIdx.x * 128;

    if (tid < 128) {
        s_rexp[tid] = 0.f; s_rsum[tid] = 0.f; s_rsame[tid] = 0.f; s_cexp[tid] = 0.f;
        s_idc[tid] = ids[col0 + tid];
    }

    // fragment base offsets; addr(ks) = base ^ (ks<<5)  (XOR distributes over
    // disjoint bit-fields of the SW128 swizzle: q = ks*2 + qlane, qlane in {0,1})
    uint32_t aD[4], bD[4];
    #pragma unroll
    for (int mt = 0; mt < 4; mt++)
        aD[mt] = swz(wm * 64 + mt * 16 + (lane & 15), lane >> 4);
    #pragma unroll
    for (int np = 0; np < 4; np++)
        bD[np] = swz(wn * 64 + np * 16 + ((lane >> 4) & 1) * 8 + (lane & 7),
                     (lane >> 3) & 1);

    float acc[4][8][4];
    #pragma unroll
    for (int mt = 0; mt < 4; mt++)
        #pragma unroll
        for (int nt = 0; nt < 8; nt++)
            #pragma unroll
            for (int c = 0; c < 4; c++) acc[mt][nt][c] = 0.f;

    // ---- async load of one K-chunk (64 bf16 = 128B per row) into stage slot ----
    auto load_stage = [&](int slot, int it) {
        const int kb = it * BK;
        const uint32_t sA = sbase + slot * STG;
        const uint32_t sB = sA + 16384;
        #pragma unroll
        for (int h = 0; h < 8; h++) {
            int f = tid + h * 128;       // 0..1023
            int r = f >> 3, q = f & 7;
            uint32_t sw = swz(r, q);
            cp16(sA + sw, &g_Abf[(size_t)(row0 + r) * DD + kb + q * 8]);
            cp16(sB + sw, &g_Bbf[(size_t)(col0 + r) * DD + kb + q * 8]);
        }
        asm volatile("cp.async.commit_group;");
    };

    load_stage(0, 0);
    load_stage(1, 1);

    #pragma unroll
    for (int it = 0; it < NIT; it++) {
        if (it + 1 < NIT) cp_wait<1>();
        else              cp_wait<0>();
        __syncthreads();
        if (it + 2 < NIT) load_stage((it + 2) % STAGES, it + 2);

        const uint32_t sA = sbase + (it % STAGES) * STG;
        const uint32_t sB = sA + 16384;
        #pragma unroll
        for (int ks = 0; ks < 4; ks++) {
            const uint32_t kx = (uint32_t)ks << 5;
            uint32_t a[4][4], b[8][2];
            #pragma unroll
            for (int mt = 0; mt < 4; mt++)
                ldsm_x4(a[mt], sA + (aD[mt] ^ kx));
            #pragma unroll
            for (int np = 0; np < 4; np++)
                ldsm_x4(&b[2 * np][0], sB + (bD[np] ^ kx));   // fills b[2np], b[2np+1]
            #pragma unroll
            for (int mt = 0; mt < 4; mt++)
                #pragma unroll
                for (int nt = 0; nt < 8; nt++)
                    mma16816(acc[mt][nt], a[mt], b[nt]);
        }
    }
    __syncthreads();

    // ---- epilogue: fragment -> row/col stats (exact fp32 diagonal patch) ----
    #pragma unroll
    for (int mt = 0; mt < 4; mt++) {
        #pragma unroll
        for (int h = 0; h < 2; h++) {
            const int rloc = wm * 64 + mt * 16 + (lane >> 2) + 8 * h;
            const int grow = row0 + rloc;
            const int rid  = ids[grow];
            const float dval = g_diag[grow];
            float rs = 0.f, rsm = 0.f, re = 0.f;
            #pragma unroll
            for (int nt = 0; nt < 8; nt++) {
                #pragma unroll
                for (int cc = 0; cc < 2; cc++) {
                    float s = acc[mt][nt][2 * h + cc];
                    int cloc = wn * 64 + nt * 8 + (lane & 3) * 2 + cc;
                    if (rid == s_idc[cloc]) {
                        if (grow == col0 + cloc) s = dval;   // exact diagonal
                        rsm += s;
                        float e = __expf((s - 1.0f) * INV_TAU);
                        re += e;
                        atomicAdd(&s_cexp[cloc], e);
                    }
                    rs += s;
                }
            }
            atomicAdd(&s_rexp[rloc],  re);
            atomicAdd(&s_rsum[rloc],  rs);
            atomicAdd(&s_rsame[rloc], rsm);
        }
    }
    __syncthreads();

    // 128 threads cover all 128 rows/cols
    atomicAdd(&g_rowexp[row0 + tid],  s_rexp[tid]);
    atomicAdd(&g_rowsum[row0 + tid],  s_rsum[tid]);
    atomicAdd(&g_rowsame[row0 + tid], s_rsame[tid]);
    atomicAdd(&g_colexp[col0 + tid],  s_cexp[tid]);
}

// ---------------- per-row CE, segment sums, triplet (block-reduced) ----------------
__global__ void finalize_kernel(const int* __restrict__ ids) {
    __shared__ float sh_segv[NS];
    __shared__ float sh_segt[NS];
    const int tid = threadIdx.x;
    if (tid < NS) { sh_segv[tid] = 0.f; sh_segt[tid] = 0.f; }
    __syncthreads();

    int i = blockIdx.x * blockDim.x + tid;
    float tri_v = 0.f, tri_n = 0.f;
    if (i < BN) {
        int id = ids[i];
        float dl = g_diag[i] * INV_TAU;
        float cev = logf(g_rowexp[i]) + INV_TAU - dl;
        float cet = logf(g_colexp[i]) + INV_TAU - dl;
        atomicAdd(&sh_segv[id], cev);
        atomicAdd(&sh_segt[id], cet);

        float cnt = g_cnt[id];
        float pos_cnt = cnt - 1.0f;
        float neg_cnt = (float)BN - cnt;
        float pos_mean = (g_rowsame[i] - g_diag[i]) / fmaxf(pos_cnt, 1.0f);
        float neg_mean = (g_rowsum[i] - g_rowsame[i]) / fmaxf(neg_cnt, 1.0f);
        float tri = fmaxf(neg_mean - pos_mean + MARGIN, 0.0f);
        bool valid = (pos_cnt > 0.0f) && (neg_cnt > 0.0f);
        tri_v = valid ? tri : 0.0f;
        tri_n = valid ? 1.0f : 0.0f;
    }
    #pragma unroll
    for (int o = 16; o > 0; o >>= 1) {
        tri_v += __shfl_xor_sync(0xffffffffu, tri_v, o);
        tri_n += __shfl_xor_sync(0xffffffffu, tri_n, o);
    }
    if ((tid & 31) == 0) {
        atomicAdd(&g_tri[0], tri_v);
        atomicAdd(&g_tri[1], tri_n);
    }
    __syncthreads();
    if (tid < NS) {
        atomicAdd(&g_segv[tid], sh_segv[tid]);
        atomicAdd(&g_segt[tid], sh_segt[tid]);
    }
}

__global__ void combine_kernel(float* __restrict__ out) {
    __shared__ float sv[NS], sn[NS];
    int s = threadIdx.x;
    float cnt = g_cnt[s];
    bool valid = cnt >= 2.0f;
    float per = (g_segv[s] + g_segt[s]) / (2.0f * fmaxf(cnt, 1.0f));
    sv[s] = valid ? per : 0.0f;
    sn[s] = valid ? 1.0f : 0.0f;
    __syncthreads();
    if (s == 0) {
        float S = 0.f, N = 0.f;
        for (int i = 0; i < NS; i++) { S += sv[i]; N += sn[i]; }
        float loss_infonce = S / fmaxf(N, 1.0f);
        float loss_triplet = g_tri[0] / fmaxf(g_tri[1], 1.0f);
        out[0] = loss_infonce + loss_triplet;
    }
}

extern "C" void kernel_launch(void* const* d_in, const int* in_sizes, int n_in,
                              void* d_out, int out_size) {
    const float* species = (const float*)d_in[0];
    const float* text    = (const float*)d_in[1];
    const int*   ids     = (const int*)d_in[2];
    float* out = (float*)d_out;

    cudaFuncSetAttribute(gemm_kernel,
                         cudaFuncAttributeMaxDynamicSharedMemorySize, SMEM_DYN);

    zero_small_kernel<<<1, 256>>>();
    prep_kernel<<<BN / 8, 256>>>(species, text, ids);
    dim3 grid(BN / 128, BN / 128);
    gemm_kernel<<<grid, 128, SMEM_DYN>>>(ids);
    finalize_kernel<<<BN / 256, 256>>>(ids);
    combine_kernel<<<1, NS>>>(out);
}

// round 11
// speedup vs baseline: 3.3078x; 3.3078x over previous
#include <cuda_runtime.h>
#include <cuda_bf16.h>
#include <math.h>
#include <stdint.h>

// ---------------- problem constants ----------------
constexpr int   BN      = 8192;
constexpr int   DD      = 256;
constexpr int   NS      = 64;
constexpr float INV_TAU = 1.0f / 0.07f;
constexpr float MARGIN  = 0.2f;

// ---------------- device scratch ----------------
__device__ __align__(16) __nv_bfloat16 g_Abf[(size_t)BN * DD];
__device__ __align__(16) __nv_bfloat16 g_Bbf[(size_t)BN * DD];

__device__ float g_rowexp[BN];
__device__ float g_colexp[BN];
__device__ float g_diag[BN];
__device__ float g_cnt[NS];
__device__ float g_segv[NS];
__device__ float g_segt[NS];
__device__ float g_tri[2];

__device__ float g_Tspc[NS * DD];   // per-species column sums of T (fp32)
__device__ float g_Tall[DD];        // total column sum of T
__device__ int   g_off[NS];
__device__ int   g_fill[NS];
__device__ int   g_perm[BN];        // rows grouped by species

// ---------------- zero scratch ----------------
constexpr int NZ = NS * DD + DD + 3 * NS + 2;   // Tspc, Tall, cnt/segv/segt, tri
__global__ void zero_misc_kernel() {
    int i = blockIdx.x * blockDim.x + threadIdx.x;
    if (i < NS * DD)                 g_Tspc[i] = 0.f;
    else if (i < NS * DD + DD)       g_Tall[i - NS * DD] = 0.f;
    else {
        int j = i - NS * DD - DD;
        if (j < NS)            g_cnt[j]  = 0.f;
        else if (j < 2 * NS)   g_segv[j - NS] = 0.f;
        else if (j < 3 * NS)   g_segt[j - 2 * NS] = 0.f;
        else if (j < 3 * NS + 2) g_tri[j - 3 * NS] = 0.f;
    }
    if (i < NS) g_fill[i] = 0;
}

// ---------------- prep: fp32->bf16, exact diag, counts, zero row stats ----------
__global__ void prep_kernel(const float* __restrict__ S,
                            const float* __restrict__ T,
                            const int* __restrict__ ids) {
    const int warp = threadIdx.x >> 5;
    const int lane = threadIdx.x & 31;
    const int row  = blockIdx.x * 8 + warp;

    const float4* s4 = (const float4*)(S + (size_t)row * DD);
    const float4* t4 = (const float4*)(T + (size_t)row * DD);
    float4 s0 = s4[lane * 2], s1 = s4[lane * 2 + 1];
    float4 t0 = t4[lane * 2], t1 = t4[lane * 2 + 1];

    __align__(16) __nv_bfloat162 sb[4];
    __align__(16) __nv_bfloat162 tb[4];
    sb[0] = __floats2bfloat162_rn(s0.x, s0.y);
    sb[1] = __floats2bfloat162_rn(s0.z, s0.w);
    sb[2] = __floats2bfloat162_rn(s1.x, s1.y);
    sb[3] = __floats2bfloat162_rn(s1.z, s1.w);
    tb[0] = __floats2bfloat162_rn(t0.x, t0.y);
    tb[1] = __floats2bfloat162_rn(t0.z, t0.w);
    tb[2] = __floats2bfloat162_rn(t1.x, t1.y);
    tb[3] = __floats2bfloat162_rn(t1.z, t1.w);
    *(uint4*)&g_Abf[(size_t)row * DD + lane * 8] = *(const uint4*)sb;
    *(uint4*)&g_Bbf[(size_t)row * DD + lane * 8] = *(const uint4*)tb;

    float dot = s0.x * t0.x + s0.y * t0.y + s0.z * t0.z + s0.w * t0.w
              + s1.x * t1.x + s1.y * t1.y + s1.z * t1.z + s1.w * t1.w;
    #pragma unroll
    for (int o = 16; o > 0; o >>= 1)
        dot += __shfl_xor_sync(0xffffffffu, dot, o);

    if (lane == 0) {
        g_diag[row] = dot;
        atomicAdd(&g_cnt[ids[row]], 1.0f);
        g_rowexp[row] = 0.f;
        g_colexp[row] = 0.f;
    }
}

// ---------------- offsets: exclusive prefix over species counts ----------------
__global__ void offsets_kernel() {
    if (threadIdx.x == 0) {
        int run = 0;
        for (int c = 0; c < NS; c++) {
            g_off[c] = run;
            run += (int)(g_cnt[c] + 0.5f);
        }
    }
}

// ---------------- scatter: group row indices by species ----------------
__global__ void scatter_kernel(const int* __restrict__ ids) {
    int i = blockIdx.x * blockDim.x + threadIdx.x;
    if (i < BN) {
        int id = ids[i];
        int pos = g_off[id] + atomicAdd(&g_fill[id], 1);
        g_perm[pos] = i;
    }
}

// ---------------- segT: per-species column sums of T (fp32) + total ----------
__global__ void segT_kernel(const float* __restrict__ T) {
    const int c = blockIdx.x;
    const int d = threadIdx.x;          // 256 dims
    const int n = (int)(g_cnt[c] + 0.5f);
    const int o = g_off[c];
    float acc = 0.f;
    #pragma unroll 4
    for (int k = 0; k < n; k++) {
        int j = g_perm[o + k];
        acc += T[(size_t)j * DD + d];
    }
    g_Tspc[c * DD + d] = acc;
    atomicAdd(&g_Tall[d], acc);
}

// ---------------- PTX helpers ----------------
__device__ __forceinline__ uint32_t smem_u32(const void* p) {
    uint32_t a;
    asm("{ .reg .u64 t; cvta.to.shared.u64 t, %1; cvt.u32.u64 %0, t; }"
        : "=r"(a) : "l"(p));
    return a;
}
__device__ __forceinline__ void cp16(uint32_t dst, const void* src) {
    asm volatile("cp.async.cg.shared.global [%0], [%1], 16;" :: "r"(dst), "l"(src));
}
__device__ __forceinline__ void ldsm_x4(uint32_t* r, uint32_t addr) {
    asm volatile("ldmatrix.sync.aligned.m8n8.x4.shared.b16 {%0,%1,%2,%3}, [%4];"
                 : "=r"(r[0]), "=r"(r[1]), "=r"(r[2]), "=r"(r[3]) : "r"(addr));
}
__device__ __forceinline__ void mma16816(float* d, const uint32_t* a, const uint32_t* b) {
    asm volatile(
        "mma.sync.aligned.m16n8k16.row.col.f32.bf16.bf16.f32 "
        "{%0,%1,%2,%3}, {%4,%5,%6,%7}, {%8,%9}, {%0,%1,%2,%3};"
        : "+f"(d[0]), "+f"(d[1]), "+f"(d[2]), "+f"(d[3])
        : "r"(a[0]), "r"(a[1]), "r"(a[2]), "r"(a[3]), "r"(b[0]), "r"(b[1]));
}
// SW128 swizzle within a [64 rows x 128B] chunk
__device__ __forceinline__ uint32_t swz(int r, int q) {
    return (uint32_t)(r * 128 + ((q ^ (r & 7)) << 4));
}

// blockexp smem layout (dynamic): A 4 chunks x 8KB, B same, then indices/stats
constexpr int SB_OFF   = 32768;
constexpr int RA_OFF   = 65536;                // 64 ints
constexpr int RB_OFF   = RA_OFF + 256;         // 64 ints
constexpr int REXP_OFF = RB_OFF + 256;         // 64 floats
constexpr int CEXP_OFF = REXP_OFF + 256;       // 64 floats
constexpr int SMEM_BE  = CEXP_OFF + 256;       // 66560 bytes

// ---------------- blockexp: same-species 64x64 sim blocks -> exp row/col sums --
// grid: (16, NS): blockIdx.x -> (mt = x&3, nt = x>>2); 128 threads (4 warps)
__global__ void __launch_bounds__(128)
blockexp_kernel() {
    const int c  = blockIdx.y;
    const int mt = blockIdx.x & 3;
    const int nt = blockIdx.x >> 2;
    const int n_c = (int)(g_cnt[c] + 0.5f);
    if (mt * 64 >= n_c || nt * 64 >= n_c) return;
    const int o = g_off[c];
    const int mrem = n_c - mt * 64;
    const int nrem = n_c - nt * 64;

    extern __shared__ char smem[];
    const uint32_t sbase = smem_u32(smem);
    int*   s_ra   = (int*)(smem + RA_OFF);
    int*   s_rb   = (int*)(smem + RB_OFF);
    float* s_rexp = (float*)(smem + REXP_OFF);
    float* s_cexp = (float*)(smem + CEXP_OFF);

    const int tid  = threadIdx.x;
    const int wid  = tid >> 5;
    const int lane = tid & 31;

    if (tid < 64) {
        int r = mt * 64 + tid;
        s_ra[tid] = g_perm[o + min(r, n_c - 1)];
        s_rexp[tid] = 0.f;
    } else {
        int t = tid - 64;
        int r = nt * 64 + t;
        s_rb[t] = g_perm[o + min(r, n_c - 1)];
        s_cexp[t] = 0.f;
    }
    __syncthreads();

    // one-shot gather load: A = S rows (64 x 512B), B = T rows (64 x 512B)
    #pragma unroll
    for (int h = 0; h < 16; h++) {
        int f = tid + h * 128;          // 0..2047
        int r  = f >> 5;
        int q  = f & 31;
        int kc = q >> 3;
        int q7 = q & 7;
        uint32_t sw = (uint32_t)(kc * 8192) + swz(r, q7);
        cp16(sbase + sw,
             &g_Abf[(size_t)s_ra[r] * DD + kc * 64 + q7 * 8]);
        cp16(sbase + SB_OFF + sw,
             &g_Bbf[(size_t)s_rb[r] * DD + kc * 64 + q7 * 8]);
    }
    asm volatile("cp.async.commit_group;");
    asm volatile("cp.async.wait_group 0;" ::: "memory");
    __syncthreads();

    // fragment base offsets (within a chunk); addr(ks2) = base ^ (ks2<<5)
    uint32_t aD, bD[4];
    aD = swz(wid * 16 + (lane & 15), lane >> 4);
    #pragma unroll
    for (int np = 0; np < 4; np++)
        bD[np] = swz(np * 16 + ((lane >> 4) & 1) * 8 + (lane & 7),
                     (lane >> 3) & 1);

    float acc[8][4];
    #pragma unroll
    for (int nt2 = 0; nt2 < 8; nt2++)
        #pragma unroll
        for (int cc = 0; cc < 4; cc++) acc[nt2][cc] = 0.f;

    #pragma unroll
    for (int ks = 0; ks < 16; ks++) {
        const uint32_t base = sbase + (uint32_t)((ks >> 2) * 8192);
        const uint32_t kx   = (uint32_t)(ks & 3) << 5;
        uint32_t a[4], b[8][2];
        ldsm_x4(a, base + (aD ^ kx));
        #pragma unroll
        for (int np = 0; np < 4; np++)
            ldsm_x4(&b[2 * np][0], base + SB_OFF + (bD[np] ^ kx));
        #pragma unroll
        for (int nt2 = 0; nt2 < 8; nt2++)
            mma16816(acc[nt2], a, b[nt2]);
    }

    // epilogue: exp over valid same-species elements, exact diag patch
    #pragma unroll
    for (int h = 0; h < 2; h++) {
        const int rloc = wid * 16 + (lane >> 2) + 8 * h;
        const bool rvalid = rloc < mrem;
        const int gr = s_ra[rloc];
        const float dval = g_diag[gr];
        float re = 0.f;
        #pragma unroll
        for (int nt2 = 0; nt2 < 8; nt2++) {
            #pragma unroll
            for (int cc = 0; cc < 2; cc++) {
                int cloc = nt2 * 8 + (lane & 3) * 2 + cc;
                if (rvalid && cloc < nrem) {
                    float s = acc[nt2][2 * h + cc];
                    if (gr == s_rb[cloc]) s = dval;
                    float e = __expf((s - 1.0f) * INV_TAU);
                    re += e;
                    atomicAdd(&s_cexp[cloc], e);
                }
            }
        }
        if (rvalid) atomicAdd(&s_rexp[rloc], re);
    }
    __syncthreads();

    if (tid < 64) {
        if (tid < mrem) atomicAdd(&g_rowexp[s_ra[tid]], s_rexp[tid]);
    } else {
        int t = tid - 64;
        if (t < nrem) atomicAdd(&g_colexp[s_rb[t]], s_cexp[t]);
    }
}

// ---------------- finalrow: rowsum/rowsame dots + CE + triplet ----------------
__global__ void finalrow_kernel(const float* __restrict__ S,
                                const int* __restrict__ ids) {
    __shared__ float sh_segv[NS];
    __shared__ float sh_segt[NS];
    __shared__ float sh_tri[2];
    const int tid  = threadIdx.x;
    const int warp = tid >> 5;
    const int lane = tid & 31;
    if (tid < NS) { sh_segv[tid] = 0.f; sh_segt[tid] = 0.f; }
    if (tid < 2)  sh_tri[tid] = 0.f;
    __syncthreads();

    const int row = blockIdx.x * 8 + warp;
    const int id  = ids[row];

    const float4* s4 = (const float4*)(S + (size_t)row * DD);
    float4 s0 = s4[lane * 2], s1 = s4[lane * 2 + 1];
    const float4* a4 = (const float4*)(g_Tall + lane * 8);
    float4 a0 = a4[0], a1 = a4[1];
    const float4* b4 = (const float4*)(g_Tspc + id * DD + lane * 8);
    float4 b0 = b4[0], b1 = b4[1];

    float rsum  = s0.x * a0.x + s0.y * a0.y + s0.z * a0.z + s0.w * a0.w
                + s1.x * a1.x + s1.y * a1.y + s1.z * a1.z + s1.w * a1.w;
    float rsame = s0.x * b0.x + s0.y * b0.y + s0.z * b0.z + s0.w * b0.w
                + s1.x * b1.x + s1.y * b1.y + s1.z * b1.z + s1.w * b1.w;
    #pragma unroll
    for (int o = 16; o > 0; o >>= 1) {
        rsum  += __shfl_xor_sync(0xffffffffu, rsum,  o);
        rsame += __shfl_xor_sync(0xffffffffu, rsame, o);
    }

    if (lane == 0) {
        float dg = g_diag[row];
        float dl = dg * INV_TAU;
        float cev = logf(g_rowexp[row]) + INV_TAU - dl;
        float cet = logf(g_colexp[row]) + INV_TAU - dl;
        atomicAdd(&sh_segv[id], cev);
        atomicAdd(&sh_segt[id], cet);

        float cnt = g_cnt[id];
        float pos_cnt = cnt - 1.0f;
        float neg_cnt = (float)BN - cnt;
        float pos_mean = (rsame - dg) / fmaxf(pos_cnt, 1.0f);
        float neg_mean = (rsum - rsame) / fmaxf(neg_cnt, 1.0f);
        float tri = fmaxf(neg_mean - pos_mean + MARGIN, 0.0f);
        bool valid = (pos_cnt > 0.0f) && (neg_cnt > 0.0f);
        if (valid) {
            atomicAdd(&sh_tri[0], tri);
            atomicAdd(&sh_tri[1], 1.0f);
        }
    }
    __syncthreads();
    if (tid < NS) {
        atomicAdd(&g_segv[tid], sh_segv[tid]);
        atomicAdd(&g_segt[tid], sh_segt[tid]);
    }
    if (tid < 2) atomicAdd(&g_tri[tid], sh_tri[tid]);
}

// ---------------- combine ----------------
__global__ void combine_kernel(float* __restrict__ out) {
    __shared__ float sv[NS], sn[NS];
    int s = threadIdx.x;
    float cnt = g_cnt[s];
    bool valid = cnt >= 2.0f;
    float per = (g_segv[s] + g_segt[s]) / (2.0f * fmaxf(cnt, 1.0f));
    sv[s] = valid ? per : 0.0f;
    sn[s] = valid ? 1.0f : 0.0f;
    __syncthreads();
    if (s == 0) {
        float S = 0.f, N = 0.f;
        for (int i = 0; i < NS; i++) { S += sv[i]; N += sn[i]; }
        float loss_infonce = S / fmaxf(N, 1.0f);
        float loss_triplet = g_tri[0] / fmaxf(g_tri[1], 1.0f);
        out[0] = loss_infonce + loss_triplet;
    }
}

extern "C" void kernel_launch(void* const* d_in, const int* in_sizes, int n_in,
                              void* d_out, int out_size) {
    const float* species = (const float*)d_in[0];
    const float* text    = (const float*)d_in[1];
    const int*   ids     = (const int*)d_in[2];
    float* out = (float*)d_out;

    cudaFuncSetAttribute(blockexp_kernel,
                         cudaFuncAttributeMaxDynamicSharedMemorySize, SMEM_BE);

    zero_misc_kernel<<<(NZ + 255) / 256, 256>>>();
    prep_kernel<<<BN / 8, 256>>>(species, text, ids);
    offsets_kernel<<<1, 32>>>();
    scatter_kernel<<<BN / 256, 256>>>(ids);
    segT_kernel<<<NS, DD>>>(text);
    blockexp_kernel<<<dim3(16, NS), 128, SMEM_BE>>>();
    finalrow_kernel<<<BN / 8, 256>>>(species, ids);
    combine_kernel<<<1, NS>>>(out);
}

// round 12
// speedup vs baseline: 3.8417x; 1.1614x over previous
#include <cuda_runtime.h>
#include <cuda_bf16.h>
#include <math.h>
#include <stdint.h>

// ---------------- problem constants ----------------
constexpr int   BN      = 8192;
constexpr int   DD      = 256;
constexpr int   NS      = 64;
constexpr float INV_TAU = 1.0f / 0.07f;
constexpr float MARGIN  = 0.2f;

// ---------------- device scratch ----------------
__device__ __align__(16) __nv_bfloat16 g_Abf[(size_t)BN * DD];
__device__ __align__(16) __nv_bfloat16 g_Bbf[(size_t)BN * DD];

__device__ float g_rowexp[BN];
__device__ float g_colexp[BN];
__device__ float g_diag[BN];
__device__ float g_cnt[NS];
__device__ int   g_cnti[NS];
__device__ float g_segv[NS];
__device__ float g_segt[NS];
__device__ float g_tri[2];
__device__ int   g_done;

__device__ float g_Tspc[NS * DD];   // per-species column sums of T (fp32)
__device__ float g_Tall[DD];        // total column sum of T
__device__ int   g_off[NS];
__device__ int   g_fill[NS];
__device__ int   g_perm[BN];        // rows grouped by species

// ---------------- setup: histogram + offsets + zero small scratch (1 block) ----
__global__ void setup_kernel(const int* __restrict__ ids) {
    __shared__ int hist[NS];
    const int tid = threadIdx.x;         // 1024 threads
    if (tid < NS) hist[tid] = 0;
    __syncthreads();
    #pragma unroll
    for (int t = 0; t < BN / 1024; t++)
        atomicAdd(&hist[ids[tid + t * 1024]], 1);
    __syncthreads();
    if (tid == 0) {
        int run = 0;
        for (int c = 0; c < NS; c++) {
            g_off[c] = run;
            int h = hist[c];
            g_cnti[c] = h;
            g_cnt[c] = (float)h;
            run += h;
        }
        g_done = 0;
        g_tri[0] = 0.f; g_tri[1] = 0.f;
    }
    if (tid < NS) {
        g_fill[tid] = 0;
        g_segv[tid] = 0.f;
        g_segt[tid] = 0.f;
    }
    if (tid < DD) g_Tall[tid] = 0.f;
}

// ---------------- prep: fp32->bf16, exact diag, scatter, zero row stats -------
__global__ void prep_kernel(const float* __restrict__ S,
                            const float* __restrict__ T,
                            const int* __restrict__ ids) {
    const int warp = threadIdx.x >> 5;
    const int lane = threadIdx.x & 31;
    const int row  = blockIdx.x * 8 + warp;

    const float4* s4 = (const float4*)(S + (size_t)row * DD);
    const float4* t4 = (const float4*)(T + (size_t)row * DD);
    float4 s0 = s4[lane * 2], s1 = s4[lane * 2 + 1];
    float4 t0 = t4[lane * 2], t1 = t4[lane * 2 + 1];

    __align__(16) __nv_bfloat162 sb[4];
    __align__(16) __nv_bfloat162 tb[4];
    sb[0] = __floats2bfloat162_rn(s0.x, s0.y);
    sb[1] = __floats2bfloat162_rn(s0.z, s0.w);
    sb[2] = __floats2bfloat162_rn(s1.x, s1.y);
    sb[3] = __floats2bfloat162_rn(s1.z, s1.w);
    tb[0] = __floats2bfloat162_rn(t0.x, t0.y);
    tb[1] = __floats2bfloat162_rn(t0.z, t0.w);
    tb[2] = __floats2bfloat162_rn(t1.x, t1.y);
    tb[3] = __floats2bfloat162_rn(t1.z, t1.w);
    *(uint4*)&g_Abf[(size_t)row * DD + lane * 8] = *(const uint4*)sb;
    *(uint4*)&g_Bbf[(size_t)row * DD + lane * 8] = *(const uint4*)tb;

    float dot = s0.x * t0.x + s0.y * t0.y + s0.z * t0.z + s0.w * t0.w
              + s1.x * t1.x + s1.y * t1.y + s1.z * t1.z + s1.w * t1.w;
    #pragma unroll
    for (int o = 16; o > 0; o >>= 1)
        dot += __shfl_xor_sync(0xffffffffu, dot, o);

    if (lane == 0) {
        g_diag[row] = dot;
        g_rowexp[row] = 0.f;
        g_colexp[row] = 0.f;
        int id = ids[row];
        int pos = g_off[id] + atomicAdd(&g_fill[id], 1);
        g_perm[pos] = row;
    }
}

// ---------------- PTX helpers ----------------
__device__ __forceinline__ uint32_t smem_u32(const void* p) {
    uint32_t a;
    asm("{ .reg .u64 t; cvta.to.shared.u64 t, %1; cvt.u32.u64 %0, t; }"
        : "=r"(a) : "l"(p));
    return a;
}
__device__ __forceinline__ void cp16(uint32_t dst, const void* src) {
    asm volatile("cp.async.cg.shared.global [%0], [%1], 16;" :: "r"(dst), "l"(src));
}
template<int N> __device__ __forceinline__ void cp_wait() {
    asm volatile("cp.async.wait_group %0;" :: "n"(N) : "memory");
}
__device__ __forceinline__ void ldsm_x4(uint32_t* r, uint32_t addr) {
    asm volatile("ldmatrix.sync.aligned.m8n8.x4.shared.b16 {%0,%1,%2,%3}, [%4];"
                 : "=r"(r[0]), "=r"(r[1]), "=r"(r[2]), "=r"(r[3]) : "r"(addr));
}
__device__ __forceinline__ void mma16816(float* d, const uint32_t* a, const uint32_t* b) {
    asm volatile(
        "mma.sync.aligned.m16n8k16.row.col.f32.bf16.bf16.f32 "
        "{%0,%1,%2,%3}, {%4,%5,%6,%7}, {%8,%9}, {%0,%1,%2,%3};"
        : "+f"(d[0]), "+f"(d[1]), "+f"(d[2]), "+f"(d[3])
        : "r"(a[0]), "r"(a[1]), "r"(a[2]), "r"(a[3]), "r"(b[0]), "r"(b[1]));
}
// SW128 swizzle within a [64 rows x 128B] chunk
__device__ __forceinline__ uint32_t swz(int r, int q) {
    return (uint32_t)(r * 128 + ((q ^ (r & 7)) << 4));
}

// blockexp smem layout (dynamic): A 4 chunks x 8KB, B same, then indices/stats
constexpr int SB_OFF   = 32768;
constexpr int RA_OFF   = 65536;                // 64 ints
constexpr int RB_OFF   = RA_OFF + 256;         // 64 ints
constexpr int REXP_OFF = RB_OFF + 256;         // 64 floats
constexpr int CEXP_OFF = REXP_OFF + 256;       // 64 floats
constexpr int PART_OFF = CEXP_OFF + 256;       // 128 floats (segT partials)
constexpr int SMEM_BE  = PART_OFF + 512;       // 67072 bytes

// ---------------- blockexp: segT slice + same-species 64x64 exp blocks --------
// grid: (16, NS); 128 threads (4 warps)
__global__ void __launch_bounds__(128)
blockexp_kernel(const float* __restrict__ T) {
    const int c = blockIdx.y;
    const int x = blockIdx.x;
    const int n_c = g_cnti[c];
    const int o   = g_off[c];

    extern __shared__ char smem[];
    const uint32_t sbase = smem_u32(smem);
    int*   s_ra   = (int*)(smem + RA_OFF);
    int*   s_rb   = (int*)(smem + RB_OFF);
    float* s_rexp = (float*)(smem + REXP_OFF);
    float* s_cexp = (float*)(smem + CEXP_OFF);
    float* s_part = (float*)(smem + PART_OFF);

    const int tid  = threadIdx.x;
    const int wid  = tid >> 5;
    const int lane = tid & 31;

    // ---- segT slice: this block sums dims [x*16, x*16+16) for species c ----
    {
        const int dl = tid & 15;
        const int s8 = tid >> 4;             // 0..7
        const int d  = x * 16 + dl;
        float p = 0.f;
        for (int k = s8; k < n_c; k += 8)
            p += T[(size_t)g_perm[o + k] * DD + d];
        s_part[tid] = p;
        __syncthreads();
        if (tid < 16) {
            float sum = 0.f;
            #pragma unroll
            for (int s = 0; s < 8; s++) sum += s_part[tid + 16 * s];
            g_Tspc[c * DD + x * 16 + tid] = sum;
            atomicAdd(&g_Tall[x * 16 + tid], sum);
        }
    }

    // ---- tile assignment ----
    const int mt = x & 3;
    const int nt = x >> 2;
    if (mt * 64 >= n_c || nt * 64 >= n_c) return;
    const int mrem = n_c - mt * 64;
    const int nrem = n_c - nt * 64;

    if (tid < 64) {
        int r = mt * 64 + tid;
        s_ra[tid] = g_perm[o + min(r, n_c - 1)];
        s_rexp[tid] = 0.f;
    } else {
        int t = tid - 64;
        int r = nt * 64 + t;
        s_rb[t] = g_perm[o + min(r, n_c - 1)];
        s_cexp[t] = 0.f;
    }
    __syncthreads();

    // gather load, split in two commit groups (K-chunks 0-1, then 2-3)
    #pragma unroll
    for (int g = 0; g < 2; g++) {
        #pragma unroll
        for (int h = 0; h < 8; h++) {
            int f  = tid + h * 128;          // 0..1023
            int r  = f >> 4;                 // 0..63
            int qq = f & 15;                 // 0..15
            int kc = g * 2 + (qq >> 3);
            int q7 = qq & 7;
            uint32_t sw = (uint32_t)(kc * 8192) + swz(r, q7);
            cp16(sbase + sw,
                 &g_Abf[(size_t)s_ra[r] * DD + kc * 64 + q7 * 8]);
            cp16(sbase + SB_OFF + sw,
                 &g_Bbf[(size_t)s_rb[r] * DD + kc * 64 + q7 * 8]);
        }
        asm volatile("cp.async.commit_group;");
    }

    // fragment base offsets (within a chunk); addr(ks2) = base ^ (ks2<<5)
    uint32_t aD, bD[4];
    aD = swz(wid * 16 + (lane & 15), lane >> 4);
    #pragma unroll
    for (int np = 0; np < 4; np++)
        bD[np] = swz(np * 16 + ((lane >> 4) & 1) * 8 + (lane & 7),
                     (lane >> 3) & 1);

    float acc[8][4];
    #pragma unroll
    for (int nt2 = 0; nt2 < 8; nt2++)
        #pragma unroll
        for (int cc = 0; cc < 4; cc++) acc[nt2][cc] = 0.f;

    cp_wait<1>();
    __syncthreads();
    #pragma unroll
    for (int ks = 0; ks < 8; ks++) {
        const uint32_t base = sbase + (uint32_t)((ks >> 2) * 8192);
        const uint32_t kx   = (uint32_t)(ks & 3) << 5;
        uint32_t a[4], b[8][2];
        ldsm_x4(a, base + (aD ^ kx));
        #pragma unroll
        for (int np = 0; np < 4; np++)
            ldsm_x4(&b[2 * np][0], base + SB_OFF + (bD[np] ^ kx));
        #pragma unroll
        for (int nt2 = 0; nt2 < 8; nt2++)
            mma16816(acc[nt2], a, b[nt2]);
    }
    cp_wait<0>();
    __syncthreads();
    #pragma unroll
    for (int ks = 8; ks < 16; ks++) {
        const uint32_t base = sbase + (uint32_t)((ks >> 2) * 8192);
        const uint32_t kx   = (uint32_t)(ks & 3) << 5;
        uint32_t a[4], b[8][2];
        ldsm_x4(a, base + (aD ^ kx));
        #pragma unroll
        for (int np = 0; np < 4; np++)
            ldsm_x4(&b[2 * np][0], base + SB_OFF + (bD[np] ^ kx));
        #pragma unroll
        for (int nt2 = 0; nt2 < 8; nt2++)
            mma16816(acc[nt2], a, b[nt2]);
    }

    // epilogue: exp over valid same-species elements, exact diag patch
    #pragma unroll
    for (int h = 0; h < 2; h++) {
        const int rloc = wid * 16 + (lane >> 2) + 8 * h;
        const bool rvalid = rloc < mrem;
        const int gr = s_ra[rloc];
        const float dval = g_diag[gr];
        float re = 0.f;
        #pragma unroll
        for (int nt2 = 0; nt2 < 8; nt2++) {
            #pragma unroll
            for (int cc = 0; cc < 2; cc++) {
                int cloc = nt2 * 8 + (lane & 3) * 2 + cc;
                if (rvalid && cloc < nrem) {
                    float s = acc[nt2][2 * h + cc];
                    if (gr == s_rb[cloc]) s = dval;
                    float e = __expf((s - 1.0f) * INV_TAU);
                    re += e;
                    atomicAdd(&s_cexp[cloc], e);
                }
            }
        }
        if (rvalid) atomicAdd(&s_rexp[rloc], re);
    }
    __syncthreads();

    if (tid < 64) {
        if (tid < mrem) atomicAdd(&g_rowexp[s_ra[tid]], s_rexp[tid]);
    } else {
        int t = tid - 64;
        if (t < nrem) atomicAdd(&g_colexp[s_rb[t]], s_cexp[t]);
    }
}

// ---------------- finalrow: dots + CE + triplet + last-block combine ----------
__global__ void finalrow_kernel(const float* __restrict__ S,
                                const int* __restrict__ ids,
                                float* __restrict__ out) {
    __shared__ float sh_segv[NS];
    __shared__ float sh_segt[NS];
    __shared__ float sh_tri[2];
    __shared__ bool  sh_last;
    const int tid  = threadIdx.x;
    const int warp = tid >> 5;
    const int lane = tid & 31;
    if (tid < NS) { sh_segv[tid] = 0.f; sh_segt[tid] = 0.f; }
    if (tid < 2)  sh_tri[tid] = 0.f;
    __syncthreads();

    const int row = blockIdx.x * 8 + warp;
    const int id  = ids[row];

    const float4* s4 = (const float4*)(S + (size_t)row * DD);
    float4 s0 = s4[lane * 2], s1 = s4[lane * 2 + 1];
    const float4* a4 = (const float4*)(g_Tall + lane * 8);
    float4 a0 = a4[0], a1 = a4[1];
    const float4* b4 = (const float4*)(g_Tspc + id * DD + lane * 8);
    float4 b0 = b4[0], b1 = b4[1];

    float rsum  = s0.x * a0.x + s0.y * a0.y + s0.z * a0.z + s0.w * a0.w
                + s1.x * a1.x + s1.y * a1.y + s1.z * a1.z + s1.w * a1.w;
    float rsame = s0.x * b0.x + s0.y * b0.y + s0.z * b0.z + s0.w * b0.w
                + s1.x * b1.x + s1.y * b1.y + s1.z * b1.z + s1.w * b1.w;
    #pragma unroll
    for (int o = 16; o > 0; o >>= 1) {
        rsum  += __shfl_xor_sync(0xffffffffu, rsum,  o);
        rsame += __shfl_xor_sync(0xffffffffu, rsame, o);
    }

    if (lane == 0) {
        float dg = g_diag[row];
        float dl = dg * INV_TAU;
        float cev = logf(g_rowexp[row]) + INV_TAU - dl;
        float cet = logf(g_colexp[row]) + INV_TAU - dl;
        atomicAdd(&sh_segv[id], cev);
        atomicAdd(&sh_segt[id], cet);

        float cnt = g_cnt[id];
        float pos_cnt = cnt - 1.0f;
        float neg_cnt = (float)BN - cnt;
        float pos_mean = (rsame - dg) / fmaxf(pos_cnt, 1.0f);
        float neg_mean = (rsum - rsame) / fmaxf(neg_cnt, 1.0f);
        float tri = fmaxf(neg_mean - pos_mean + MARGIN, 0.0f);
        bool valid = (pos_cnt > 0.0f) && (neg_cnt > 0.0f);
        if (valid) {
            atomicAdd(&sh_tri[0], tri);
            atomicAdd(&sh_tri[1], 1.0f);
        }
    }
    __syncthreads();
    if (tid < NS) {
        atomicAdd(&g_segv[tid], sh_segv[tid]);
        atomicAdd(&g_segt[tid], sh_segt[tid]);
    }
    if (tid < 2) atomicAdd(&g_tri[tid], sh_tri[tid]);

    // last-block combine
    __threadfence();
    __syncthreads();
    if (tid == 0)
        sh_last = (atomicAdd(&g_done, 1) == (int)gridDim.x - 1);
    __syncthreads();
    if (sh_last && tid == 0) {
        __threadfence();
        float Ssum = 0.f, Nval = 0.f;
        for (int c = 0; c < NS; c++) {
            float cnt = g_cnt[c];
            if (cnt >= 2.0f) {
                Ssum += (g_segv[c] + g_segt[c]) / (2.0f * cnt);
                Nval += 1.0f;
            }
        }
        float loss_infonce = Ssum / fmaxf(Nval, 1.0f);
        float loss_triplet = g_tri[0] / fmaxf(g_tri[1], 1.0f);
        out[0] = loss_infonce + loss_triplet;
    }
}

extern "C" void kernel_launch(void* const* d_in, const int* in_sizes, int n_in,
                              void* d_out, int out_size) {
    const float* species = (const float*)d_in[0];
    const float* text    = (const float*)d_in[1];
    const int*   ids     = (const int*)d_in[2];
    float* out = (float*)d_out;

    cudaFuncSetAttribute(blockexp_kernel,
                         cudaFuncAttributeMaxDynamicSharedMemorySize, SMEM_BE);

    setup_kernel<<<1, 1024>>>(ids);
    prep_kernel<<<BN / 8, 256>>>(species, text, ids);
    blockexp_kernel<<<dim3(16, NS), 128, SMEM_BE>>>(text);
    finalrow_kernel<<<BN / 8, 256>>>(species, ids, out);
}